// round 15
// baseline (speedup 1.0000x reference)
#include <cuda_runtime.h>
#include <math.h>

// B=32, N=256, D=256, H=8, K=16
#define BB 32
#define NN 256
#define HH 8
#define KK 16

#define QOFF 16777216        // B*H*N*N
#define SCALAR_OFF 33554432  // 2*B*H*N*N
#define LOG_EPS -18.420680744f   // log(1e-8)

// scratch (device globals — no allocation allowed)
__device__ __align__(16) float d_Wt[512 * 16];   // W_eff transposed: [j][k]
__device__ __align__(16) float d_beff[16];
__device__ __align__(16) float d_S[BB * NN * KK];
__device__ __align__(16) float d_G[HH * KK * KK];
__device__ __align__(16) float d_SG[BB * HH * NN * KK];  // 2*S@G, [b][h][n][l]
__device__ float d_greg;
__device__ float d_orth[BB];
__device__ float d_usage[BB];
__device__ int d_cnt;   // zero-init; reset by the finalizing block each launch

// ---------------------------------------------------------------------------
// Kernel PRE: blocks 0-127 compute W_eff (4-way d-reduction split);
// block 128: registerized sinkhorn(G)+g_reg (warps 0-3), b_eff (warps 4-7).
// ---------------------------------------------------------------------------
__global__ void __launch_bounds__(256) k_pre(const float* __restrict__ Wslot,
                      const float* __restrict__ Wfus,
                      const float* __restrict__ Gp,
                      const float* __restrict__ bfus,
                      const float* __restrict__ bslot) {
    int tid = threadIdx.x;
    if (blockIdx.x < 128) {
        __shared__ float ws[256];
        __shared__ float part[4][64];
        int k = blockIdx.x >> 3, seg = blockIdx.x & 7;
        ws[tid] = Wslot[k * 256 + tid];
        __syncthreads();
        int jl = tid & 63, dq = tid >> 6;
        int j = seg * 64 + jl;
        const float* col = Wfus + j + (dq * 64) * 512;
        const float* wsh = ws + dq * 64;
        float a0 = 0.f, a1 = 0.f, a2 = 0.f, a3 = 0.f;
#pragma unroll
        for (int d0 = 0; d0 < 64; d0 += 32) {
            float v[32];
#pragma unroll
            for (int u = 0; u < 32; u++) v[u] = col[(d0 + u) * 512];
#pragma unroll
            for (int u = 0; u < 32; u += 4) {
                a0 += wsh[d0 + u]     * v[u];
                a1 += wsh[d0 + u + 1] * v[u + 1];
                a2 += wsh[d0 + u + 2] * v[u + 2];
                a3 += wsh[d0 + u + 3] * v[u + 3];
            }
        }
        part[dq][jl] = (a0 + a1) + (a2 + a3);
        __syncthreads();
        if (tid < 64) {
            float s = (part[0][tid] + part[1][tid]) + (part[2][tid] + part[3][tid]);
            d_Wt[(seg * 64 + tid) * 16 + k] = s;
        }
        return;
    }

    // ---- block 128 ----
    __shared__ __align__(16) float sv[128 * 16];
    __shared__ float red[8];

    if (tid >= 128) {
        int w = (tid >> 5) - 4;
        int lane = tid & 31;
        int kg = w * 4;
        float acc[4] = {0.f, 0.f, 0.f, 0.f};
#pragma unroll
        for (int i = 0; i < 8; i++) {
            int d = i * 32 + lane;
            float bf = bfus[d];
#pragma unroll
            for (int kk = 0; kk < 4; kk++)
                acc[kk] += Wslot[(kg + kk) * 256 + d] * bf;
        }
#pragma unroll
        for (int o = 16; o; o >>= 1)
#pragma unroll
            for (int kk = 0; kk < 4; kk++)
                acc[kk] += __shfl_xor_sync(0xffffffffu, acc[kk], o);
        if (lane < 4) d_beff[kg + lane] = acc[lane] + bslot[kg + lane];
    } else {
        int r = tid;
        float g[16];
        {
            const float4* gp = (const float4*)(Gp + r * 16);
            float4 v0 = gp[0], v1 = gp[1], v2 = gp[2], v3 = gp[3];
            g[0] = v0.x; g[1] = v0.y; g[2] = v0.z; g[3] = v0.w;
            g[4] = v1.x; g[5] = v1.y; g[6] = v1.z; g[7] = v1.w;
            g[8] = v2.x; g[9] = v2.y; g[10] = v2.z; g[11] = v2.w;
            g[12] = v3.x; g[13] = v3.y; g[14] = v3.z; g[15] = v3.w;
        }
        float m = g[0];
#pragma unroll
        for (int j = 1; j < 16; j++) m = fmaxf(m, g[j]);
        float s = 0.f;
#pragma unroll
        for (int j = 0; j < 16; j++) { g[j] = __expf(g[j] - m); s += g[j]; }
        float inv = 1.f / s;
#pragma unroll
        for (int j = 0; j < 16; j++) g[j] = fmaxf(g[j] * inv, 1e-6f);

#pragma unroll 1
        for (int it = 0; it < 10; ++it) {
            float rs = 0.f;
#pragma unroll
            for (int j = 0; j < 16; j++) rs += g[j];
            float rinv = 1.f / (rs + 1e-6f);
#pragma unroll
            for (int j = 0; j < 16; j++) g[j] *= rinv;
            float c[16];
#pragma unroll
            for (int j = 0; j < 16; j++) c[j] = g[j];
#pragma unroll
            for (int o = 8; o; o >>= 1)
#pragma unroll
                for (int j = 0; j < 16; j++)
                    c[j] += __shfl_xor_sync(0xffffffffu, c[j], o);
#pragma unroll
            for (int j = 0; j < 16; j++) g[j] *= 1.f / (c[j] + 1e-6f);
        }
        g[r & 15] = 0.f;
        {
            float4* gp = (float4*)(d_G + r * 16);
            gp[0] = make_float4(g[0], g[1], g[2], g[3]);
            gp[1] = make_float4(g[4], g[5], g[6], g[7]);
            gp[2] = make_float4(g[8], g[9], g[10], g[11]);
            gp[3] = make_float4(g[12], g[13], g[14], g[15]);
        }
        float sq = 0.f;
#pragma unroll
        for (int j = 0; j < 16; j++) sq += g[j] * g[j];
#pragma unroll
        for (int o = 8; o; o >>= 1) sq += __shfl_xor_sync(0xffffffffu, sq, o);
        float ninv = 1.f / fmaxf(sqrtf(sq), 1e-8f);
        float4* svp = (float4*)&sv[r * 16];
        svp[0] = make_float4(g[0] * ninv, g[1] * ninv, g[2] * ninv, g[3] * ninv);
        svp[1] = make_float4(g[4] * ninv, g[5] * ninv, g[6] * ninv, g[7] * ninv);
        svp[2] = make_float4(g[8] * ninv, g[9] * ninv, g[10] * ninv, g[11] * ninv);
        svp[3] = make_float4(g[12] * ninv, g[13] * ninv, g[14] * ninv, g[15] * ninv);
    }
    __syncthreads();

    {   // g_reg
        int il = tid >> 4, j = tid & 15;
        float wv = 0.f;
#pragma unroll
        for (int h = 0; h < 8; h++) wv += sv[(h * 16 + il) * 16 + j];
        float sq = wv * wv;
#pragma unroll
        for (int o = 16; o; o >>= 1) sq += __shfl_xor_sync(0xffffffffu, sq, o);
        if ((tid & 31) == 0) red[tid >> 5] = sq;
        __syncthreads();
        if (tid == 0) {
            float t = 0.f;
            for (int i = 0; i < 8; i++) t += red[i];
            d_greg = 0.02f * (t - 8.0f) / 56.0f;
        }
    }
}

// ---------------------------------------------------------------------------
// Split-exchange reduction: a[16] partials per lane -> returns total for
// k = lane&15 (duplicated across halves). 31 shfl instead of 80.
// ---------------------------------------------------------------------------
__device__ __forceinline__ float warp_reduce_k16(float* a, int lane) {
#pragma unroll
    for (int k = 0; k < 16; k++) a[k] += __shfl_xor_sync(0xffffffffu, a[k], 16);
    bool b3 = (lane >> 3) & 1;
#pragma unroll
    for (int j = 0; j < 8; j++) {
        float give = b3 ? a[j] : a[j + 8];
        float recv = __shfl_xor_sync(0xffffffffu, give, 8);
        a[j] = (b3 ? a[j + 8] : a[j]) + recv;
    }
    bool b2 = (lane >> 2) & 1;
#pragma unroll
    for (int j = 0; j < 4; j++) {
        float give = b2 ? a[j] : a[j + 4];
        float recv = __shfl_xor_sync(0xffffffffu, give, 4);
        a[j] = (b2 ? a[j + 4] : a[j]) + recv;
    }
    bool b1 = (lane >> 1) & 1;
#pragma unroll
    for (int j = 0; j < 2; j++) {
        float give = b1 ? a[j] : a[j + 2];
        float recv = __shfl_xor_sync(0xffffffffu, give, 2);
        a[j] = (b1 ? a[j + 2] : a[j]) + recv;
    }
    bool b0 = lane & 1;
    float give = b0 ? a[0] : a[1];
    float recv = __shfl_xor_sync(0xffffffffu, give, 1);
    return (b0 ? a[1] : a[0]) + recv;
}

// ---------------------------------------------------------------------------
// Kernel C: S = softmax(X @ W_eff^T + b_eff)  AND  SG = 2*(S @ G[h]) for all h.
// grid 256 x 256 (block = b*8 + chunk, 32 rows each).
// ---------------------------------------------------------------------------
__global__ void __launch_bounds__(256) k_S(const float* __restrict__ desc,
                                           const float* __restrict__ nv) {
    __shared__ float WtG[512 * 20];       // 40KB: Wt first, then G (8KB)
    __shared__ float Ss2[32 * 17];
    __shared__ float be[16];
    int tid = threadIdx.x;
    const float4* src = (const float4*)d_Wt;
#pragma unroll
    for (int q = 0; q < 8; q++) {
        int idx = tid + q * 256;
        float4 v = src[idx];
        int j = idx >> 2, c = idx & 3;
        *(float4*)&WtG[j * 20 + c * 4] = v;
    }
    if (tid < 16) be[tid] = d_beff[tid];
    __syncthreads();

    int warp = tid >> 5, lane = tid & 31;
    int kown = lane & 15;
#pragma unroll 1
    for (int pp = 0; pp < 2; ++pp) {
        int rl = warp * 4 + pp * 2;
        int row = blockIdx.x * 32 + rl;
        const float* xd0 = desc + row * 256;
        const float* xn0 = nv + row * 256;
        float a0[16], a1[16];
#pragma unroll
        for (int k = 0; k < 16; k++) { a0[k] = 0.f; a1[k] = 0.f; }
#pragma unroll
        for (int jj = 0; jj < 16; jj++) {
            int j = lane + jj * 32;
            float x0 = (jj < 8) ? xd0[j] : xn0[j - 256];
            float x1 = (jj < 8) ? xd0[j + 256] : xn0[j];
            const float* wp = &WtG[j * 20];
            float4 w0 = *(const float4*)(wp);
            float4 w1 = *(const float4*)(wp + 4);
            float4 w2 = *(const float4*)(wp + 8);
            float4 w3 = *(const float4*)(wp + 12);
            a0[0] += x0 * w0.x; a0[1] += x0 * w0.y; a0[2] += x0 * w0.z; a0[3] += x0 * w0.w;
            a0[4] += x0 * w1.x; a0[5] += x0 * w1.y; a0[6] += x0 * w1.z; a0[7] += x0 * w1.w;
            a0[8] += x0 * w2.x; a0[9] += x0 * w2.y; a0[10] += x0 * w2.z; a0[11] += x0 * w2.w;
            a0[12] += x0 * w3.x; a0[13] += x0 * w3.y; a0[14] += x0 * w3.z; a0[15] += x0 * w3.w;
            a1[0] += x1 * w0.x; a1[1] += x1 * w0.y; a1[2] += x1 * w0.z; a1[3] += x1 * w0.w;
            a1[4] += x1 * w1.x; a1[5] += x1 * w1.y; a1[6] += x1 * w1.z; a1[7] += x1 * w1.w;
            a1[8] += x1 * w2.x; a1[9] += x1 * w2.y; a1[10] += x1 * w2.z; a1[11] += x1 * w2.w;
            a1[12] += x1 * w3.x; a1[13] += x1 * w3.y; a1[14] += x1 * w3.z; a1[15] += x1 * w3.w;
        }
        float v0 = warp_reduce_k16(a0, lane) + be[kown];
        float v1 = warp_reduce_k16(a1, lane) + be[kown];
        float m0 = v0, m1 = v1;
#pragma unroll
        for (int o = 8; o; o >>= 1) {
            m0 = fmaxf(m0, __shfl_xor_sync(0xffffffffu, m0, o));
            m1 = fmaxf(m1, __shfl_xor_sync(0xffffffffu, m1, o));
        }
        float e0 = __expf(v0 - m0), e1 = __expf(v1 - m1);
        float s0 = e0, s1 = e1;
#pragma unroll
        for (int o = 8; o; o >>= 1) {
            s0 += __shfl_xor_sync(0xffffffffu, s0, o);
            s1 += __shfl_xor_sync(0xffffffffu, s1, o);
        }
        if (lane < 16) {
            Ss2[rl * 17 + lane] = e0 / s0;
            Ss2[(rl + 1) * 17 + lane] = e1 / s1;
        }
    }
    __syncthreads();

    // cooperative store of S (STG.64, coalesced)
    {
        int nl = tid >> 3, k0 = (tid & 7) * 2;
        float2 v = make_float2(Ss2[nl * 17 + k0], Ss2[nl * 17 + k0 + 1]);
        *(float2*)&d_S[(blockIdx.x * 32 + nl) * 16 + k0] = v;
    }

    // load G (2048 floats = 512 float4s) into the now-free Wt region.
    // tid<128, 4 float4s each: 128*4 = 512 float4s — FULL coverage.
    float* Gsh = WtG;
    if (tid < 128) {
        const float4* gp = (const float4*)d_G;
#pragma unroll
        for (int i = 0; i < 4; i++)
            ((float4*)Gsh)[tid * 4 + i] = gp[tid * 4 + i];
    }
    __syncthreads();

    // SG phase: warp = head h (G loads broadcast), lane = local row.
    {
        int h = warp, nl = lane;
        float sg[16];
#pragma unroll
        for (int l = 0; l < 16; l++) sg[l] = 0.f;
#pragma unroll
        for (int k = 0; k < 16; k++) {
            float sk = Ss2[nl * 17 + k];
            const float4* gr = (const float4*)&Gsh[h * 256 + k * 16];
            float4 g0 = gr[0], g1 = gr[1], g2 = gr[2], g3 = gr[3];
            sg[0] += sk * g0.x; sg[1] += sk * g0.y; sg[2] += sk * g0.z; sg[3] += sk * g0.w;
            sg[4] += sk * g1.x; sg[5] += sk * g1.y; sg[6] += sk * g1.z; sg[7] += sk * g1.w;
            sg[8] += sk * g2.x; sg[9] += sk * g2.y; sg[10] += sk * g2.z; sg[11] += sk * g2.w;
            sg[12] += sk * g3.x; sg[13] += sk * g3.y; sg[14] += sk * g3.z; sg[15] += sk * g3.w;
        }
        int b = blockIdx.x >> 3, chunk = blockIdx.x & 7;
        float4* dst = (float4*)&d_SG[(((size_t)b * 8 + h) * 256 + chunk * 32 + nl) * 16];
        dst[0] = make_float4(2.f * sg[0], 2.f * sg[1], 2.f * sg[2], 2.f * sg[3]);
        dst[1] = make_float4(2.f * sg[4], 2.f * sg[5], 2.f * sg[6], 2.f * sg[7]);
        dst[2] = make_float4(2.f * sg[8], 2.f * sg[9], 2.f * sg[10], 2.f * sg[11]);
        dst[3] = make_float4(2.f * sg[12], 2.f * sg[13], 2.f * sg[14], 2.f * sg[15]);
    }
}

// ---------------------------------------------------------------------------
// Kernel D (dominant): per (b,h,chunk of 32 rows): A = SG_pre @ S^T, row softmax,
// write Q and bias_log (__stcs). grid 2048 x 256, 4 CTAs/SM (quarter-K phases,
// live regs ~62).  [champion config; SG prologue widened to float4, tid<128]
// ---------------------------------------------------------------------------
__global__ void __launch_bounds__(256, 4) k_Q(float* __restrict__ out) {
    __shared__ __align__(16) float Ss[256 * 20];
    __shared__ __align__(16) float SGs[32 * 16];
    __shared__ float red[8];
    __shared__ float us[16];
    int tid = threadIdx.x;
    int bh = blockIdx.x >> 3;
    int chunk = blockIdx.x & 7;
    int b = bh >> 3;

    const float4* sp = (const float4*)(d_S + b * 4096);
#pragma unroll
    for (int q = 0; q < 4; q++) {
        float4 v = sp[tid * 4 + q];
        *(float4*)&Ss[tid * 20 + q * 4] = v;
    }
    if (tid < 128) {   // 128 x float4 = 512 floats = full SG chunk
        float4 v = ((const float4*)(d_SG + (size_t)bh * 4096 + chunk * 512))[tid];
        *(float4*)&SGs[tid * 4] = v;
    }
    __syncthreads();

    int warp = tid >> 5, lane = tid & 31;
    int r0 = warp * 4;

    float acc[4][8];
#pragma unroll
    for (int r = 0; r < 4; r++)
#pragma unroll
        for (int c = 0; c < 8; c++) acc[r][c] = 0.f;

#pragma unroll
    for (int qf = 0; qf < 4; qf++) {
        float sg[4][4];
#pragma unroll
        for (int r = 0; r < 4; r++) {
            float4 g = *(const float4*)&SGs[(r0 + r) * 16 + qf * 4];
            sg[r][0] = g.x; sg[r][1] = g.y; sg[r][2] = g.z; sg[r][3] = g.w;
        }
#pragma unroll
        for (int c = 0; c < 8; c++) {
            int m = lane + c * 32;
            float4 sa = *(const float4*)&Ss[m * 20 + qf * 4];
#pragma unroll
            for (int r = 0; r < 4; r++) {
                acc[r][c] += sg[r][0] * sa.x;
                acc[r][c] += sg[r][1] * sa.y;
                acc[r][c] += sg[r][2] * sa.z;
                acc[r][c] += sg[r][3] * sa.w;
            }
        }
    }

#pragma unroll
    for (int r = 0; r < 4; r++) {
        float mx = acc[r][0];
#pragma unroll
        for (int c = 1; c < 8; c++) mx = fmaxf(mx, acc[r][c]);
#pragma unroll
        for (int o = 16; o; o >>= 1)
            mx = fmaxf(mx, __shfl_xor_sync(0xffffffffu, mx, o));
        float e[8], s = 0.f;
#pragma unroll
        for (int c = 0; c < 8; c++) { e[c] = __expf(acc[r][c] - mx); s += e[c]; }
#pragma unroll
        for (int o = 16; o; o >>= 1) s += __shfl_xor_sync(0xffffffffu, s, o);
        float inv = 1.f / s;
        float lz = __logf(s);
        int nglob = bh * 256 + chunk * 32 + r0 + r;
        float* bp = out + (size_t)nglob * 256;          // bias_log
        float* qp = out + QOFF + (size_t)nglob * 256;   // Q
#pragma unroll
        for (int c = 0; c < 8; c++) {
            int m = lane + c * 32;
            __stcs(&qp[m], e[c] * inv);
            __stcs(&bp[m], fmaxf(acc[r][c] - mx - lz, LOG_EPS));
        }
    }

    // ---- regularizer epilogue on the 32 (h==0, chunk==0) blocks ----
    if ((blockIdx.x & 63) == 0) {
        int k = tid >> 4, l = tid & 15;
        float a = 0.f;
#pragma unroll 8
        for (int n = 0; n < 256; n++) a += Ss[n * 20 + k] * Ss[n * 20 + l];
        a *= (1.0f / 256.f);
        float off = (k != l) ? a : 0.f;
        float sq = off * off;
#pragma unroll
        for (int o = 16; o; o >>= 1) sq += __shfl_xor_sync(0xffffffffu, sq, o);
        if ((tid & 31) == 0) red[tid >> 5] = sq;

        if (tid < 16) {
            float u = 0.f;
#pragma unroll 8
            for (int n = 0; n < 256; n++) u += Ss[n * 20 + tid];
            us[tid] = u * (1.0f / 256.f);
        }
        __syncthreads();
        if (tid == 0) {
            float t = 0.f;
            for (int i = 0; i < 8; i++) t += red[i];
            d_orth[b] = 0.1f * t / 8192.0f;
            float usum = 0.f;
            for (int kk = 0; kk < 16; kk++) usum += us[kk];
            float lK = logf(1.0f / 16.0f);
            float kl = 0.f;
            for (int kk = 0; kk < 16; kk++) {
                float uc = fmaxf(us[kk] / (usum + 1e-8f), 1e-8f);
                kl += uc * (logf(uc) - lK);
            }
            d_usage[b] = 0.1f * kl / 32.0f;
            __threadfence();
            int prev = atomicAdd(&d_cnt, 1);
            if (prev == 31) {
                __threadfence();
                float tt = d_greg;
                for (int bb = 0; bb < 32; bb++) tt += d_orth[bb];
                for (int bb = 0; bb < 32; bb++) tt += d_usage[bb];
                out[SCALAR_OFF] = tt;
                d_cnt = 0;
            }
        }
    }
}

// ---------------------------------------------------------------------------
extern "C" void kernel_launch(void* const* d_in, const int* in_sizes, int n_in,
                              void* d_out, int out_size) {
    const float* desc  = (const float*)d_in[0];
    const float* nv    = (const float*)d_in[1];
    const float* Wfus  = (const float*)d_in[2];
    const float* bfus  = (const float*)d_in[3];
    const float* Wslot = (const float*)d_in[4];
    const float* bslot = (const float*)d_in[5];
    const float* Gp    = (const float*)d_in[6];
    float* out = (float*)d_out;

    k_pre<<<129, 256>>>(Wslot, Wfus, Gp, bfus, bslot);
    k_S<<<256, 256>>>(desc, nv);
    k_Q<<<BB * HH * 8, 256>>>(out);
}

// round 16
// speedup vs baseline: 1.0289x; 1.0289x over previous
#include <cuda_runtime.h>
#include <math.h>

// B=32, N=256, D=256, H=8, K=16
#define BB 32
#define NN 256
#define HH 8
#define KK 16

#define QOFF 16777216        // B*H*N*N
#define SCALAR_OFF 33554432  // 2*B*H*N*N
#define LOG_EPS -18.420680744f   // log(1e-8)

// scratch (device globals — no allocation allowed)
__device__ __align__(16) float d_Wt[512 * 16];   // W_eff transposed: [j][k]
__device__ __align__(16) float d_beff[16];
__device__ __align__(16) float d_S[BB * NN * KK];
__device__ __align__(16) float d_G[HH * KK * KK];
__device__ float d_greg;
__device__ float d_orth[BB];
__device__ float d_usage[BB];
__device__ int d_cnt;   // zero-init; reset by the finalizing block each launch

// ---------------------------------------------------------------------------
// Kernel PRE: blocks 0-127 compute W_eff (4-way d-reduction split);
// block 128: registerized sinkhorn(G)+g_reg (warps 0-3), b_eff (warps 4-7).
// ---------------------------------------------------------------------------
__global__ void __launch_bounds__(256) k_pre(const float* __restrict__ Wslot,
                      const float* __restrict__ Wfus,
                      const float* __restrict__ Gp,
                      const float* __restrict__ bfus,
                      const float* __restrict__ bslot) {
    int tid = threadIdx.x;
    if (blockIdx.x < 128) {
        __shared__ float ws[256];
        __shared__ float part[4][64];
        int k = blockIdx.x >> 3, seg = blockIdx.x & 7;
        ws[tid] = Wslot[k * 256 + tid];
        __syncthreads();
        int jl = tid & 63, dq = tid >> 6;
        int j = seg * 64 + jl;
        const float* col = Wfus + j + (dq * 64) * 512;
        const float* wsh = ws + dq * 64;
        float a0 = 0.f, a1 = 0.f, a2 = 0.f, a3 = 0.f;
#pragma unroll
        for (int d0 = 0; d0 < 64; d0 += 32) {
            float v[32];
#pragma unroll
            for (int u = 0; u < 32; u++) v[u] = col[(d0 + u) * 512];
#pragma unroll
            for (int u = 0; u < 32; u += 4) {
                a0 += wsh[d0 + u]     * v[u];
                a1 += wsh[d0 + u + 1] * v[u + 1];
                a2 += wsh[d0 + u + 2] * v[u + 2];
                a3 += wsh[d0 + u + 3] * v[u + 3];
            }
        }
        part[dq][jl] = (a0 + a1) + (a2 + a3);
        __syncthreads();
        if (tid < 64) {
            float s = (part[0][tid] + part[1][tid]) + (part[2][tid] + part[3][tid]);
            d_Wt[(seg * 64 + tid) * 16 + k] = s;
        }
        return;
    }

    // ---- block 128 ----
    __shared__ __align__(16) float sv[128 * 16];
    __shared__ float red[8];

    if (tid >= 128) {
        int w = (tid >> 5) - 4;
        int lane = tid & 31;
        int kg = w * 4;
        float acc[4] = {0.f, 0.f, 0.f, 0.f};
#pragma unroll
        for (int i = 0; i < 8; i++) {
            int d = i * 32 + lane;
            float bf = bfus[d];
#pragma unroll
            for (int kk = 0; kk < 4; kk++)
                acc[kk] += Wslot[(kg + kk) * 256 + d] * bf;
        }
#pragma unroll
        for (int o = 16; o; o >>= 1)
#pragma unroll
            for (int kk = 0; kk < 4; kk++)
                acc[kk] += __shfl_xor_sync(0xffffffffu, acc[kk], o);
        if (lane < 4) d_beff[kg + lane] = acc[lane] + bslot[kg + lane];
    } else {
        int r = tid;
        float g[16];
        {
            const float4* gp = (const float4*)(Gp + r * 16);
            float4 v0 = gp[0], v1 = gp[1], v2 = gp[2], v3 = gp[3];
            g[0] = v0.x; g[1] = v0.y; g[2] = v0.z; g[3] = v0.w;
            g[4] = v1.x; g[5] = v1.y; g[6] = v1.z; g[7] = v1.w;
            g[8] = v2.x; g[9] = v2.y; g[10] = v2.z; g[11] = v2.w;
            g[12] = v3.x; g[13] = v3.y; g[14] = v3.z; g[15] = v3.w;
        }
        float m = g[0];
#pragma unroll
        for (int j = 1; j < 16; j++) m = fmaxf(m, g[j]);
        float s = 0.f;
#pragma unroll
        for (int j = 0; j < 16; j++) { g[j] = __expf(g[j] - m); s += g[j]; }
        float inv = 1.f / s;
#pragma unroll
        for (int j = 0; j < 16; j++) g[j] = fmaxf(g[j] * inv, 1e-6f);

#pragma unroll 1
        for (int it = 0; it < 10; ++it) {
            float rs = 0.f;
#pragma unroll
            for (int j = 0; j < 16; j++) rs += g[j];
            float rinv = 1.f / (rs + 1e-6f);
#pragma unroll
            for (int j = 0; j < 16; j++) g[j] *= rinv;
            float c[16];
#pragma unroll
            for (int j = 0; j < 16; j++) c[j] = g[j];
#pragma unroll
            for (int o = 8; o; o >>= 1)
#pragma unroll
                for (int j = 0; j < 16; j++)
                    c[j] += __shfl_xor_sync(0xffffffffu, c[j], o);
#pragma unroll
            for (int j = 0; j < 16; j++) g[j] *= 1.f / (c[j] + 1e-6f);
        }
        g[r & 15] = 0.f;
        {
            float4* gp = (float4*)(d_G + r * 16);
            gp[0] = make_float4(g[0], g[1], g[2], g[3]);
            gp[1] = make_float4(g[4], g[5], g[6], g[7]);
            gp[2] = make_float4(g[8], g[9], g[10], g[11]);
            gp[3] = make_float4(g[12], g[13], g[14], g[15]);
        }
        float sq = 0.f;
#pragma unroll
        for (int j = 0; j < 16; j++) sq += g[j] * g[j];
#pragma unroll
        for (int o = 8; o; o >>= 1) sq += __shfl_xor_sync(0xffffffffu, sq, o);
        float ninv = 1.f / fmaxf(sqrtf(sq), 1e-8f);
        float4* svp = (float4*)&sv[r * 16];
        svp[0] = make_float4(g[0] * ninv, g[1] * ninv, g[2] * ninv, g[3] * ninv);
        svp[1] = make_float4(g[4] * ninv, g[5] * ninv, g[6] * ninv, g[7] * ninv);
        svp[2] = make_float4(g[8] * ninv, g[9] * ninv, g[10] * ninv, g[11] * ninv);
        svp[3] = make_float4(g[12] * ninv, g[13] * ninv, g[14] * ninv, g[15] * ninv);
    }
    __syncthreads();

    {   // g_reg
        int il = tid >> 4, j = tid & 15;
        float wv = 0.f;
#pragma unroll
        for (int h = 0; h < 8; h++) wv += sv[(h * 16 + il) * 16 + j];
        float sq = wv * wv;
#pragma unroll
        for (int o = 16; o; o >>= 1) sq += __shfl_xor_sync(0xffffffffu, sq, o);
        if ((tid & 31) == 0) red[tid >> 5] = sq;
        __syncthreads();
        if (tid == 0) {
            float t = 0.f;
            for (int i = 0; i < 8; i++) t += red[i];
            d_greg = 0.02f * (t - 8.0f) / 56.0f;
        }
    }
}

// ---------------------------------------------------------------------------
// Split-exchange reduction: a[16] partials per lane -> returns total for
// k = lane&15 (duplicated across halves). 31 shfl instead of 80.
// ---------------------------------------------------------------------------
__device__ __forceinline__ float warp_reduce_k16(float* a, int lane) {
#pragma unroll
    for (int k = 0; k < 16; k++) a[k] += __shfl_xor_sync(0xffffffffu, a[k], 16);
    bool b3 = (lane >> 3) & 1;
#pragma unroll
    for (int j = 0; j < 8; j++) {
        float give = b3 ? a[j] : a[j + 8];
        float recv = __shfl_xor_sync(0xffffffffu, give, 8);
        a[j] = (b3 ? a[j + 8] : a[j]) + recv;
    }
    bool b2 = (lane >> 2) & 1;
#pragma unroll
    for (int j = 0; j < 4; j++) {
        float give = b2 ? a[j] : a[j + 4];
        float recv = __shfl_xor_sync(0xffffffffu, give, 4);
        a[j] = (b2 ? a[j + 4] : a[j]) + recv;
    }
    bool b1 = (lane >> 1) & 1;
#pragma unroll
    for (int j = 0; j < 2; j++) {
        float give = b1 ? a[j] : a[j + 2];
        float recv = __shfl_xor_sync(0xffffffffu, give, 2);
        a[j] = (b1 ? a[j + 2] : a[j]) + recv;
    }
    bool b0 = lane & 1;
    float give = b0 ? a[0] : a[1];
    float recv = __shfl_xor_sync(0xffffffffu, give, 1);
    return (b0 ? a[1] : a[0]) + recv;
}

// ---------------------------------------------------------------------------
// Kernel C: S = softmax(X @ W_eff^T + b_eff) ONLY (SG moved into k_Q).
// grid 256 x 256 (block covers 32 rows).
// ---------------------------------------------------------------------------
__global__ void __launch_bounds__(256) k_S(const float* __restrict__ desc,
                                           const float* __restrict__ nv) {
    __shared__ float WtG[512 * 20];       // 40KB Wt tile
    __shared__ float Ss2[32 * 17];
    __shared__ float be[16];
    int tid = threadIdx.x;
    const float4* src = (const float4*)d_Wt;
#pragma unroll
    for (int q = 0; q < 8; q++) {
        int idx = tid + q * 256;
        float4 v = src[idx];
        int j = idx >> 2, c = idx & 3;
        *(float4*)&WtG[j * 20 + c * 4] = v;
    }
    if (tid < 16) be[tid] = d_beff[tid];
    __syncthreads();

    int warp = tid >> 5, lane = tid & 31;
    int kown = lane & 15;
#pragma unroll 1
    for (int pp = 0; pp < 2; ++pp) {
        int rl = warp * 4 + pp * 2;
        int row = blockIdx.x * 32 + rl;
        const float* xd0 = desc + row * 256;
        const float* xn0 = nv + row * 256;
        float a0[16], a1[16];
#pragma unroll
        for (int k = 0; k < 16; k++) { a0[k] = 0.f; a1[k] = 0.f; }
#pragma unroll
        for (int jj = 0; jj < 16; jj++) {
            int j = lane + jj * 32;
            float x0 = (jj < 8) ? xd0[j] : xn0[j - 256];
            float x1 = (jj < 8) ? xd0[j + 256] : xn0[j];
            const float* wp = &WtG[j * 20];
            float4 w0 = *(const float4*)(wp);
            float4 w1 = *(const float4*)(wp + 4);
            float4 w2 = *(const float4*)(wp + 8);
            float4 w3 = *(const float4*)(wp + 12);
            a0[0] += x0 * w0.x; a0[1] += x0 * w0.y; a0[2] += x0 * w0.z; a0[3] += x0 * w0.w;
            a0[4] += x0 * w1.x; a0[5] += x0 * w1.y; a0[6] += x0 * w1.z; a0[7] += x0 * w1.w;
            a0[8] += x0 * w2.x; a0[9] += x0 * w2.y; a0[10] += x0 * w2.z; a0[11] += x0 * w2.w;
            a0[12] += x0 * w3.x; a0[13] += x0 * w3.y; a0[14] += x0 * w3.z; a0[15] += x0 * w3.w;
            a1[0] += x1 * w0.x; a1[1] += x1 * w0.y; a1[2] += x1 * w0.z; a1[3] += x1 * w0.w;
            a1[4] += x1 * w1.x; a1[5] += x1 * w1.y; a1[6] += x1 * w1.z; a1[7] += x1 * w1.w;
            a1[8] += x1 * w2.x; a1[9] += x1 * w2.y; a1[10] += x1 * w2.z; a1[11] += x1 * w2.w;
            a1[12] += x1 * w3.x; a1[13] += x1 * w3.y; a1[14] += x1 * w3.z; a1[15] += x1 * w3.w;
        }
        float v0 = warp_reduce_k16(a0, lane) + be[kown];
        float v1 = warp_reduce_k16(a1, lane) + be[kown];
        float m0 = v0, m1 = v1;
#pragma unroll
        for (int o = 8; o; o >>= 1) {
            m0 = fmaxf(m0, __shfl_xor_sync(0xffffffffu, m0, o));
            m1 = fmaxf(m1, __shfl_xor_sync(0xffffffffu, m1, o));
        }
        float e0 = __expf(v0 - m0), e1 = __expf(v1 - m1);
        float s0 = e0, s1 = e1;
#pragma unroll
        for (int o = 8; o; o >>= 1) {
            s0 += __shfl_xor_sync(0xffffffffu, s0, o);
            s1 += __shfl_xor_sync(0xffffffffu, s1, o);
        }
        if (lane < 16) {
            Ss2[rl * 17 + lane] = e0 / s0;
            Ss2[(rl + 1) * 17 + lane] = e1 / s1;
        }
    }
    __syncthreads();

    // cooperative store of S (STG.64, coalesced)
    {
        int nl = tid >> 3, k0 = (tid & 7) * 2;
        float2 v = make_float2(Ss2[nl * 17 + k0], Ss2[nl * 17 + k0 + 1]);
        *(float2*)&d_S[(blockIdx.x * 32 + nl) * 16 + k0] = v;
    }
}

// ---------------------------------------------------------------------------
// Kernel D (dominant): per (b,h,chunk of 32 rows): SG computed INLINE from the
// resident S tile + G[h] (no d_SG round-trip), then A = SG @ S^T, row softmax,
// write Q and bias_log (__stcs). grid 2048 x 256, 4 CTAs/SM.
// ---------------------------------------------------------------------------
__global__ void __launch_bounds__(256, 4) k_Q(float* __restrict__ out) {
    __shared__ __align__(16) float Ss[256 * 20];
    __shared__ __align__(16) float SGs[32 * 16];
    __shared__ __align__(16) float Gs[256];
    __shared__ float red[8];
    __shared__ float us[16];
    int tid = threadIdx.x;
    int bh = blockIdx.x >> 3;
    int chunk = blockIdx.x & 7;
    int b = bh >> 3, h = bh & 7;

    const float4* sp = (const float4*)(d_S + b * 4096);
#pragma unroll
    for (int q = 0; q < 4; q++) {
        float4 v = sp[tid * 4 + q];
        *(float4*)&Ss[tid * 20 + q * 4] = v;
    }
    Gs[tid] = d_G[h * 256 + tid];
    __syncthreads();

    // inline SG: 512 elements over 256 threads (2 each), pre-scaled by 1/tau=2
#pragma unroll
    for (int r = 0; r < 2; r++) {
        int e = tid + r * 256;
        int nl = e >> 4, l = e & 15;
        const float* srow = &Ss[(chunk * 32 + nl) * 20];
        float s = 0.f;
#pragma unroll
        for (int k = 0; k < 16; k++) s += srow[k] * Gs[k * 16 + l];
        SGs[nl * 16 + l] = 2.0f * s;
    }
    __syncthreads();

    int warp = tid >> 5, lane = tid & 31;
    int r0 = warp * 4;

    float acc[4][8];
#pragma unroll
    for (int r = 0; r < 4; r++)
#pragma unroll
        for (int c = 0; c < 8; c++) acc[r][c] = 0.f;

#pragma unroll
    for (int qf = 0; qf < 4; qf++) {
        float sg[4][4];
#pragma unroll
        for (int r = 0; r < 4; r++) {
            float4 g = *(const float4*)&SGs[(r0 + r) * 16 + qf * 4];
            sg[r][0] = g.x; sg[r][1] = g.y; sg[r][2] = g.z; sg[r][3] = g.w;
        }
#pragma unroll
        for (int c = 0; c < 8; c++) {
            int m = lane + c * 32;
            float4 sa = *(const float4*)&Ss[m * 20 + qf * 4];
#pragma unroll
            for (int r = 0; r < 4; r++) {
                acc[r][c] += sg[r][0] * sa.x;
                acc[r][c] += sg[r][1] * sa.y;
                acc[r][c] += sg[r][2] * sa.z;
                acc[r][c] += sg[r][3] * sa.w;
            }
        }
    }

#pragma unroll
    for (int r = 0; r < 4; r++) {
        float mx = acc[r][0];
#pragma unroll
        for (int c = 1; c < 8; c++) mx = fmaxf(mx, acc[r][c]);
#pragma unroll
        for (int o = 16; o; o >>= 1)
            mx = fmaxf(mx, __shfl_xor_sync(0xffffffffu, mx, o));
        float e[8], s = 0.f;
#pragma unroll
        for (int c = 0; c < 8; c++) { e[c] = __expf(acc[r][c] - mx); s += e[c]; }
#pragma unroll
        for (int o = 16; o; o >>= 1) s += __shfl_xor_sync(0xffffffffu, s, o);
        float inv = 1.f / s;
        float lz = __logf(s);
        int nglob = bh * 256 + chunk * 32 + r0 + r;
        float* bp = out + (size_t)nglob * 256;          // bias_log
        float* qp = out + QOFF + (size_t)nglob * 256;   // Q
#pragma unroll
        for (int c = 0; c < 8; c++) {
            int m = lane + c * 32;
            __stcs(&qp[m], e[c] * inv);
            __stcs(&bp[m], fmaxf(acc[r][c] - mx - lz, LOG_EPS));
        }
    }

    // ---- regularizer epilogue on the 32 (h==0, chunk==0) blocks ----
    if ((blockIdx.x & 63) == 0) {
        int k = tid >> 4, l = tid & 15;
        float a = 0.f;
#pragma unroll 8
        for (int n = 0; n < 256; n++) a += Ss[n * 20 + k] * Ss[n * 20 + l];
        a *= (1.0f / 256.f);
        float off = (k != l) ? a : 0.f;
        float sq = off * off;
#pragma unroll
        for (int o = 16; o; o >>= 1) sq += __shfl_xor_sync(0xffffffffu, sq, o);
        if ((tid & 31) == 0) red[tid >> 5] = sq;

        if (tid < 16) {
            float u = 0.f;
#pragma unroll 8
            for (int n = 0; n < 256; n++) u += Ss[n * 20 + tid];
            us[tid] = u * (1.0f / 256.f);
        }
        __syncthreads();
        if (tid == 0) {
            float t = 0.f;
            for (int i = 0; i < 8; i++) t += red[i];
            d_orth[b] = 0.1f * t / 8192.0f;
            float usum = 0.f;
            for (int kk = 0; kk < 16; kk++) usum += us[kk];
            float lK = logf(1.0f / 16.0f);
            float kl = 0.f;
            for (int kk = 0; kk < 16; kk++) {
                float uc = fmaxf(us[kk] / (usum + 1e-8f), 1e-8f);
                kl += uc * (logf(uc) - lK);
            }
            d_usage[b] = 0.1f * kl / 32.0f;
            __threadfence();
            int prev = atomicAdd(&d_cnt, 1);
            if (prev == 31) {
                __threadfence();
                float tt = d_greg;
                for (int bb = 0; bb < 32; bb++) tt += d_orth[bb];
                for (int bb = 0; bb < 32; bb++) tt += d_usage[bb];
                out[SCALAR_OFF] = tt;
                d_cnt = 0;
            }
        }
    }
}

// ---------------------------------------------------------------------------
extern "C" void kernel_launch(void* const* d_in, const int* in_sizes, int n_in,
                              void* d_out, int out_size) {
    const float* desc  = (const float*)d_in[0];
    const float* nv    = (const float*)d_in[1];
    const float* Wfus  = (const float*)d_in[2];
    const float* bfus  = (const float*)d_in[3];
    const float* Wslot = (const float*)d_in[4];
    const float* bslot = (const float*)d_in[5];
    const float* Gp    = (const float*)d_in[6];
    float* out = (float*)d_out;

    k_pre<<<129, 256>>>(Wslot, Wfus, Gp, bfus, bslot);
    k_S<<<256, 256>>>(desc, nv);
    k_Q<<<BB * HH * 8, 256>>>(out);
}